// round 2
// baseline (speedup 1.0000x reference)
#include <cuda_runtime.h>
#include <math.h>

#define FEAT_I 512
#define H_DIM  1024
#define CODE   640
#define CODE_G 320
#define FEAT_G 256
#define B_     8
#define T_     4096
#define N_     (B_ * T_)          // 32768
#define Q_ELEMS ((size_t)B_ * 512 * T_)   // 16,777,216

// Scratch (allocation-free rule: __device__ globals)
__device__ float g_h[(size_t)N_ * H_DIM];        // 128 MB
__device__ float g_logits[(size_t)N_ * CODE];    //  80 MB

// ---------------------------------------------------------------------------
// GEMM1: h = relu(x @ W1 + b1),  x[m,k] = series[b, k, t]  (m = b*T + t)
// 128x128 tile, BK=8, 256 threads, 8x8 microtile.
// A-tile load is t-contiguous (coalesced) because series is (B, F, T).
// ---------------------------------------------------------------------------
__global__ __launch_bounds__(256, 2)
void gemm1_kernel(const float* __restrict__ series,
                  const float* __restrict__ W1,
                  const float* __restrict__ b1)
{
    __shared__ float As[8][128];   // k-major
    __shared__ float Bs[8][128];

    const int tid   = threadIdx.x;
    const int jBase = blockIdx.x * 128;          // 0..896
    const int mBase = blockIdx.y * 128;          // 0..32640
    const int b     = mBase / T_;                // 4096 % 128 == 0 -> whole tile in one b
    const int t0    = mBase % T_;

    const float* Abase = series + (size_t)b * FEAT_I * T_ + t0;

    const int lk  = tid >> 5;          // 0..7
    const int lm4 = (tid & 31) * 4;    // 0..124
    const int tm  = tid >> 4;          // 0..15
    const int tn  = tid & 15;          // 0..15

    float acc[8][8];
#pragma unroll
    for (int i = 0; i < 8; i++)
#pragma unroll
        for (int j = 0; j < 8; j++) acc[i][j] = 0.f;

    for (int k0 = 0; k0 < FEAT_I; k0 += 8) {
        *(float4*)&As[lk][lm4] = *(const float4*)&Abase[(size_t)(k0 + lk) * T_ + lm4];
        *(float4*)&Bs[lk][lm4] = *(const float4*)&W1[(size_t)(k0 + lk) * H_DIM + jBase + lm4];
        __syncthreads();
#pragma unroll
        for (int k = 0; k < 8; k++) {
            float a[8], bb[8];
            *(float4*)&a[0]  = *(float4*)&As[k][tm * 8];
            *(float4*)&a[4]  = *(float4*)&As[k][tm * 8 + 4];
            *(float4*)&bb[0] = *(float4*)&Bs[k][tn * 8];
            *(float4*)&bb[4] = *(float4*)&Bs[k][tn * 8 + 4];
#pragma unroll
            for (int i = 0; i < 8; i++)
#pragma unroll
                for (int j = 0; j < 8; j++)
                    acc[i][j] = fmaf(a[i], bb[j], acc[i][j]);
        }
        __syncthreads();
    }

    // epilogue: +bias, relu, store (vectorized)
    float bias[8];
#pragma unroll
    for (int j = 0; j < 8; j++) bias[j] = b1[jBase + tn * 8 + j];
#pragma unroll
    for (int i = 0; i < 8; i++) {
        const int m = mBase + tm * 8 + i;
        float v[8];
#pragma unroll
        for (int j = 0; j < 8; j++) {
            float z = acc[i][j] + bias[j];
            v[j] = z > 0.f ? z : 0.f;
        }
        float* hrow = g_h + (size_t)m * H_DIM + jBase + tn * 8;
        *(float4*)&hrow[0] = *(float4*)&v[0];
        *(float4*)&hrow[4] = *(float4*)&v[4];
    }
}

// ---------------------------------------------------------------------------
// GEMM2: z = h @ W2 + b2 + gumbel(u)   stored as perturbed logits (argmax-
// equivalent to the reference's softmax path; /TAU dropped: monotone).
// A (g_h) is row-major -> A-tile loaded along k (float4), stored padded
// [128][12] to keep compute LDS conflict-light.
// ---------------------------------------------------------------------------
__global__ __launch_bounds__(256, 2)
void gemm2_kernel(const float* __restrict__ W2,
                  const float* __restrict__ b2,
                  const float* __restrict__ gumbel_u)
{
    __shared__ float As[128][12];  // m-major, pad 12 floats/row (48B)
    __shared__ float Bs[8][128];

    const int tid   = threadIdx.x;
    const int jBase = blockIdx.x * 128;     // 0..512 (grid.x = 5 -> 640 cols)
    const int mBase = blockIdx.y * 128;

    const int lm  = tid >> 1;          // 0..127
    const int lp  = (tid & 1) * 4;     // 0 / 4
    const int lk  = tid >> 5;
    const int lj4 = (tid & 31) * 4;
    const int tm  = tid >> 4;
    const int tn  = tid & 15;

    float acc[8][8];
#pragma unroll
    for (int i = 0; i < 8; i++)
#pragma unroll
        for (int j = 0; j < 8; j++) acc[i][j] = 0.f;

    for (int k0 = 0; k0 < H_DIM; k0 += 8) {
        *(float4*)&As[lm][lp]  = *(const float4*)&g_h[(size_t)(mBase + lm) * H_DIM + k0 + lp];
        *(float4*)&Bs[lk][lj4] = *(const float4*)&W2[(size_t)(k0 + lk) * CODE + jBase + lj4];
        __syncthreads();
#pragma unroll
        for (int k = 0; k < 8; k++) {
            float a[8], bb[8];
#pragma unroll
            for (int i = 0; i < 8; i++) a[i] = As[tm * 8 + i][k];
            *(float4*)&bb[0] = *(float4*)&Bs[k][tn * 8];
            *(float4*)&bb[4] = *(float4*)&Bs[k][tn * 8 + 4];
#pragma unroll
            for (int i = 0; i < 8; i++)
#pragma unroll
                for (int j = 0; j < 8; j++)
                    acc[i][j] = fmaf(a[i], bb[j], acc[i][j]);
        }
        __syncthreads();
    }

    // epilogue: + bias + gumbel noise, store perturbed logits
#pragma unroll
    for (int i = 0; i < 8; i++) {
        const int row = mBase + tm * 8 + i;
        const size_t base = (size_t)row * CODE + jBase + tn * 8;
#pragma unroll
        for (int j = 0; j < 8; j++) {
            const int col = jBase + tn * 8 + j;
            float z = acc[i][j] + b2[col];
            float u = gumbel_u[base + j];
            float g = -logf(-logf(u + 1e-10f) + 1e-10f);
            g_logits[base + j] = z + g;
        }
    }
}

// ---------------------------------------------------------------------------
// Kernel 3: per-(n, group) argmax over 320 perturbed logits (first-index
// tiebreak, matching jnp.argmax), then codebook gather with t-coalesced
// transposed writes into q_series; idx written (as float) after q region.
// grid: (T/32, B, GROUP), block 256 (8 warps; 4 rows/warp for argmax).
// ---------------------------------------------------------------------------
__global__ __launch_bounds__(256)
void argmax_gather_kernel(const float* __restrict__ codebook,
                          float* __restrict__ out)
{
    const int t0 = blockIdx.x * 32;
    const int b  = blockIdx.y;
    const int g  = blockIdx.z;

    __shared__ int s_idx[32];

    const int tid  = threadIdx.x;
    const int lane = tid & 31;
    const int w    = tid >> 5;

#pragma unroll
    for (int rr = 0; rr < 4; rr++) {
        const int tl = w * 4 + rr;
        const int n  = b * T_ + t0 + tl;
        const float* lp = g_logits + (size_t)n * CODE + g * CODE_G;
        float best = -INFINITY;
        int   bi   = 0;
        for (int c = lane; c < CODE_G; c += 32) {
            float v = lp[c];
            if (v > best) { best = v; bi = c; }   // strided ascending: strict > keeps first
        }
#pragma unroll
        for (int off = 16; off; off >>= 1) {
            float ov = __shfl_down_sync(0xffffffffu, best, off);
            int   oi = __shfl_down_sync(0xffffffffu, bi,   off);
            if (ov > best || (ov == best && oi < bi)) { best = ov; bi = oi; }
        }
        if (lane == 0) {
            s_idx[tl] = bi;
            out[Q_ELEMS + (size_t)n * 2 + g] = (float)bi;   // maxidx_series[b,t,g]
        }
    }
    __syncthreads();

    const int tx = tid & 31;    // t within tile -> coalesced writes
    const int fy = tid >> 5;    // 8 f-lanes
    const int idx = s_idx[tx];
    const float* cbrow = codebook + ((size_t)g * CODE_G + idx) * FEAT_G;
    float* outb = out + ((size_t)b * 512 + g * FEAT_G) * T_ + t0;
    for (int f = fy; f < FEAT_G; f += 8)
        outb[(size_t)f * T_ + tx] = cbrow[f];   // q_series[b, g*256+f, t0+tx]
}

// ---------------------------------------------------------------------------
extern "C" void kernel_launch(void* const* d_in, const int* in_sizes, int n_in,
                              void* d_out, int out_size)
{
    const float* series   = (const float*)d_in[0];
    const float* gumbel_u = (const float*)d_in[1];
    const float* W1       = (const float*)d_in[2];
    const float* b1       = (const float*)d_in[3];
    const float* W2       = (const float*)d_in[4];
    const float* b2       = (const float*)d_in[5];
    const float* codebook = (const float*)d_in[6];
    float* out = (float*)d_out;

    gemm1_kernel<<<dim3(H_DIM / 128, N_ / 128), 256>>>(series, W1, b1);
    gemm2_kernel<<<dim3(CODE / 128, N_ / 128), 256>>>(W2, b2, gumbel_u);
    argmax_gather_kernel<<<dim3(T_ / 32, B_, 2), 256>>>(codebook, out);
}